// round 7
// baseline (speedup 1.0000x reference)
#include <cuda_runtime.h>
#include <cuda_fp16.h>
#include <cuda_bf16.h>
#include <cstdint>

// KANLayer: out[b] = sum_{d,h} tanh(x[b,d]*w1[d,h] + b1[d,h]) * w2[d,h] + sum_d b2[d]
// B=65536, D=256, H=16.
//
// f16x2 pipeline: params staged into smem as __half2 (h, h+1 packed).
// Per 2 terms: HFMA2(arg) -> tanh.approx.f16x2 (1 MUFU, 2 results) -> HFMA2(prod).
// Products accumulate in two f16x2 chains of 4 per d, combined with HADD2,
// then up-converted and added to an fp32 accumulator (fixed order, deterministic).
// MUFU: 8 ops per d (16 terms) = 4 cyc/term per SMSP -- the binding pipe.

#define D_DIM 256
#define H_DIM 16
#define DH    (D_DIM * H_DIM)    // 4096
#define B_DIM 65536
#define TPB   224                // 7 warps; grid=293 -> 2 balanced waves

__device__ __forceinline__ __half2 htanh2(__half2 v) {
    unsigned vi = *reinterpret_cast<unsigned*>(&v);
    unsigned ro;
    asm("tanh.approx.f16x2 %0, %1;" : "=r"(ro) : "r"(vi));
    return *reinterpret_cast<__half2*>(&ro);
}

__global__ __launch_bounds__(TPB) void kan_main(const float* __restrict__ x,
                                                const float* __restrict__ w1,
                                                const float* __restrict__ b1,
                                                const float* __restrict__ w2,
                                                const float* __restrict__ b2,
                                                float* __restrict__ out) {
    // 3 x 4096 halves = 24 KB
    __shared__ __half2 s_w1[DH / 2];
    __shared__ __half2 s_b1[DH / 2];
    __shared__ __half2 s_w2[DH / 2];
    __shared__ float   s_red[8];

    const int t    = threadIdx.x;
    const int lane = t & 31;
    const int wid  = t >> 5;

    // ---- Sum(b2): fixed-order deterministic reduce (b2 has 256 elems, TPB=224).
    float myb2 = b2[t];
    if (t < 32) myb2 += b2[224 + t];
    #pragma unroll
    for (int off = 16; off > 0; off >>= 1)
        myb2 += __shfl_xor_sync(0xFFFFFFFFu, myb2, off);
    if (lane == 0) s_red[wid] = myb2;    // 7 warp partials
    __syncthreads();
    float C = 0.0f;
    #pragma unroll
    for (int i = 0; i < 7; ++i) C += s_red[i];

    // ---- Stage params into smem as packed half2 (lo = h even, hi = h odd).
    {
        const float4* gw1 = reinterpret_cast<const float4*>(w1);
        const float4* gb1 = reinterpret_cast<const float4*>(b1);
        const float4* gw2 = reinterpret_cast<const float4*>(w2);
        for (int i = t; i < DH / 4; i += TPB) {
            float4 a = gw1[i];
            float4 bb = gb1[i];
            float4 c = gw2[i];
            s_w1[2 * i]     = __floats2half2_rn(a.x, a.y);
            s_w1[2 * i + 1] = __floats2half2_rn(a.z, a.w);
            s_b1[2 * i]     = __floats2half2_rn(bb.x, bb.y);
            s_b1[2 * i + 1] = __floats2half2_rn(bb.z, bb.w);
            s_w2[2 * i]     = __floats2half2_rn(c.x, c.y);
            s_w2[2 * i + 1] = __floats2half2_rn(c.z, c.w);
        }
    }
    __syncthreads();

    // ---- One thread per output row. Whole warp walks the same d sequence,
    // so every param LDS is a broadcast (conflict-free).
    const int b = blockIdx.x * TPB + t;
    if (b >= B_DIM) return;

    const float4* xr = reinterpret_cast<const float4*>(x) + (size_t)b * (D_DIM / 4);

    float acc = 0.0f;

    #pragma unroll 2
    for (int d4 = 0; d4 < D_DIM / 4; ++d4) {
        float4 xv = xr[d4];
        #pragma unroll
        for (int j = 0; j < 4; ++j) {
            const float xd = (j == 0) ? xv.x : (j == 1) ? xv.y : (j == 2) ? xv.z : xv.w;
            const int d = d4 * 4 + j;
            const __half2* w1p = &s_w1[d * (H_DIM / 2)];
            const __half2* b1p = &s_b1[d * (H_DIM / 2)];
            const __half2* w2p = &s_w2[d * (H_DIM / 2)];

            const __half2 xx = __float2half2_rn(xd);

            __half2 c0 = __float2half2_rn(0.0f);
            __half2 c1 = __float2half2_rn(0.0f);
            #pragma unroll
            for (int q = 0; q < 4; ++q) {
                __half2 a0 = __hfma2(xx, w1p[q], b1p[q]);
                __half2 t0 = htanh2(a0);
                c0 = __hfma2(t0, w2p[q], c0);
            }
            #pragma unroll
            for (int q = 4; q < 8; ++q) {
                __half2 a1 = __hfma2(xx, w1p[q], b1p[q]);
                __half2 t1 = htanh2(a1);
                c1 = __hfma2(t1, w2p[q], c1);
            }
            __half2 cs = __hadd2(c0, c1);
            float2 f = __half22float2(cs);
            acc += f.x + f.y;
        }
    }

    out[b] = acc + C;
}

extern "C" void kernel_launch(void* const* d_in, const int* in_sizes, int n_in,
                              void* d_out, int out_size) {
    const float* x  = (const float*)d_in[0];
    const float* w1 = (const float*)d_in[1];
    const float* b1 = (const float*)d_in[2];
    const float* w2 = (const float*)d_in[3];
    const float* b2 = (const float*)d_in[4];
    float* out = (float*)d_out;

    const int grid = (B_DIM + TPB - 1) / TPB;   // 293
    kan_main<<<grid, TPB>>>(x, w1, b1, w2, b2, out);
}